// round 4
// baseline (speedup 1.0000x reference)
#include <cuda_runtime.h>
#include <cstdint>

// Fixed shapes: B=4, S=1024, E=1024, width=768 -> H=12, D=64
#define Bq   4
#define Sq   1024
#define Eq   1024
#define Wd   768
#define Hh   12
#define Dd   64
#define BSq  (Bq*Sq)            // 4096
#define NZ   (Bq*Hh)            // 48
#define OUT_ELEMS   ((long long)BSq*Wd)        // 3,145,728
#define ATTN_ELEMS  ((long long)NZ*Sq*Sq)      // 50,331,648

// ---------------- scratch (device globals; no runtime allocation) ----------
__device__ __align__(16) float g_q[BSq*Wd];
__device__ __align__(16) float g_k[BSq*Wd];
__device__ __align__(16) float g_v[BSq*Wd];
__device__ __align__(16) float g_ctx[BSq*Wd];
__device__ __align__(16) float g_rm[NZ*Sq];      // per-row global max
__device__ __align__(16) float g_ri[NZ*Sq];      // per-row 1/sum
__device__ __align__(16) float g_attn_fallback[NZ*Sq*Sq];

// ---------------- packed f32x2 helpers -------------------------------------
__device__ __forceinline__ unsigned long long pack2(float x, float y) {
    unsigned long long r;
    asm("mov.b64 %0, {%1, %2};" : "=l"(r) : "f"(x), "f"(y));
    return r;
}
__device__ __forceinline__ void unpack2(unsigned long long v, float& x, float& y) {
    asm("mov.b64 {%0, %1}, %2;" : "=f"(x), "=f"(y) : "l"(v));
}
__device__ __forceinline__ unsigned long long ffma2(unsigned long long a,
                                                    unsigned long long b,
                                                    unsigned long long c) {
    unsigned long long d;
    asm("fma.rn.f32x2 %0, %1, %2, %3;" : "=l"(d) : "l"(a), "l"(b), "l"(c));
    return d;
}

// ---------------------------------------------------------------------------
// 128x128 NT GEMM body (for projections): C += A[128,K] * B[128,K]^T
// ---------------------------------------------------------------------------
__device__ __forceinline__ void gemm_nt_128(const float* __restrict__ A, int lda,
                                            const float* __restrict__ B, int ldb,
                                            int K, unsigned long long (&acc)[8][4],
                                            float (&As)[16][132], float (&Bs)[16][132]) {
    const int t  = threadIdx.x;
    const int tr = t >> 4;
    const int tc = t & 15;
    const int lr = t >> 2;
    const int lk = (t & 3) << 2;

    for (int k0 = 0; k0 < K; k0 += 16) {
        float4 a0 = *(const float4*)(A + (size_t)lr * lda + k0 + lk);
        float4 a1 = *(const float4*)(A + (size_t)(lr + 64) * lda + k0 + lk);
        float4 b0 = *(const float4*)(B + (size_t)lr * ldb + k0 + lk);
        float4 b1 = *(const float4*)(B + (size_t)(lr + 64) * ldb + k0 + lk);
        As[lk+0][lr] = a0.x; As[lk+1][lr] = a0.y; As[lk+2][lr] = a0.z; As[lk+3][lr] = a0.w;
        As[lk+0][lr+64] = a1.x; As[lk+1][lr+64] = a1.y; As[lk+2][lr+64] = a1.z; As[lk+3][lr+64] = a1.w;
        Bs[lk+0][lr] = b0.x; Bs[lk+1][lr] = b0.y; Bs[lk+2][lr] = b0.z; Bs[lk+3][lr] = b0.w;
        Bs[lk+0][lr+64] = b1.x; Bs[lk+1][lr+64] = b1.y; Bs[lk+2][lr+64] = b1.z; Bs[lk+3][lr+64] = b1.w;
        __syncthreads();

        #pragma unroll
        for (int kk = 0; kk < 16; kk++) {
            float4 x0 = *(const float4*)&As[kk][tr * 8];
            float4 x1 = *(const float4*)&As[kk][tr * 8 + 4];
            float4 y0 = *(const float4*)&Bs[kk][tc * 8];
            float4 y1 = *(const float4*)&Bs[kk][tc * 8 + 4];
            unsigned long long bp[4] = { pack2(y0.x, y0.y), pack2(y0.z, y0.w),
                                         pack2(y1.x, y1.y), pack2(y1.z, y1.w) };
            float av[8] = { x0.x, x0.y, x0.z, x0.w, x1.x, x1.y, x1.z, x1.w };
            #pragma unroll
            for (int i = 0; i < 8; i++) {
                unsigned long long ap = pack2(av[i], av[i]);
                #pragma unroll
                for (int j = 0; j < 4; j++)
                    acc[i][j] = ffma2(ap, bp[j], acc[i][j]);
            }
        }
        __syncthreads();
    }
}

// ---------------------------------------------------------------------------
// 128x64 NT GEMM body (score tiles, K=64): C += A[128,64] * B[64,64]^T
// thread micro-tile: 8 rows x 4 cols. acc[i][0]=(c0,c1), acc[i][1]=(c2,c3)
// ---------------------------------------------------------------------------
__device__ __forceinline__ void gemm_s_tile(const float* __restrict__ A, int lda,
                                            const float* __restrict__ B, int ldb,
                                            unsigned long long (&acc)[8][2],
                                            float (&As)[16][132], float (&Bs)[16][68]) {
    const int t  = threadIdx.x;
    const int lr = t >> 2;
    const int lk = (t & 3) << 2;
    const int row0 = (t >> 4) * 8;
    const int col0 = (t & 15) * 4;

    for (int k0 = 0; k0 < Dd; k0 += 16) {
        float4 a0 = *(const float4*)(A + (size_t)lr * lda + k0 + lk);
        float4 a1 = *(const float4*)(A + (size_t)(lr + 64) * lda + k0 + lk);
        float4 b0 = *(const float4*)(B + (size_t)lr * ldb + k0 + lk);   // 64 B-rows
        As[lk+0][lr] = a0.x; As[lk+1][lr] = a0.y; As[lk+2][lr] = a0.z; As[lk+3][lr] = a0.w;
        As[lk+0][lr+64] = a1.x; As[lk+1][lr+64] = a1.y; As[lk+2][lr+64] = a1.z; As[lk+3][lr+64] = a1.w;
        Bs[lk+0][lr] = b0.x; Bs[lk+1][lr] = b0.y; Bs[lk+2][lr] = b0.z; Bs[lk+3][lr] = b0.w;
        __syncthreads();

        #pragma unroll
        for (int kk = 0; kk < 16; kk++) {
            float4 x0 = *(const float4*)&As[kk][row0];
            float4 x1 = *(const float4*)&As[kk][row0 + 4];
            float4 y  = *(const float4*)&Bs[kk][col0];
            unsigned long long bp0 = pack2(y.x, y.y);
            unsigned long long bp1 = pack2(y.z, y.w);
            float av[8] = { x0.x, x0.y, x0.z, x0.w, x1.x, x1.y, x1.z, x1.w };
            #pragma unroll
            for (int i = 0; i < 8; i++) {
                unsigned long long ap = pack2(av[i], av[i]);
                acc[i][0] = ffma2(ap, bp0, acc[i][0]);
                acc[i][1] = ffma2(ap, bp1, acc[i][1]);
            }
        }
        __syncthreads();
    }
}

// ---------------------------------------------------------------------------
// Kernel 1: fused QKV projections. grid(6, 32, 3), block(256)
// ---------------------------------------------------------------------------
__global__ __launch_bounds__(256)
void qkv_kernel(const float* __restrict__ x,
                const float* __restrict__ qw, const float* __restrict__ qb,
                const float* __restrict__ kw, const float* __restrict__ kb,
                const float* __restrict__ vw, const float* __restrict__ vb) {
    __shared__ float As[16][132], Bs[16][132];
    const float* W; const float* bias; float* out;
    if (blockIdx.z == 0)      { W = qw; bias = qb; out = g_q; }
    else if (blockIdx.z == 1) { W = kw; bias = kb; out = g_k; }
    else                      { W = vw; bias = vb; out = g_v; }

    const int i0 = blockIdx.y * 128;
    const int n0 = blockIdx.x * 128;
    unsigned long long acc[8][4];
    #pragma unroll
    for (int i = 0; i < 8; i++)
        #pragma unroll
        for (int j = 0; j < 4; j++) acc[i][j] = 0ull;

    gemm_nt_128(x + (size_t)i0 * Eq, Eq, W + (size_t)n0 * Eq, Eq, Wd, acc, As, Bs);

    const int row0 = (threadIdx.x >> 4) * 8;
    const int col0 = (threadIdx.x & 15) * 8;
    #pragma unroll
    for (int i = 0; i < 8; i++) {
        float c[8];
        #pragma unroll
        for (int j = 0; j < 4; j++) unpack2(acc[i][j], c[2*j], c[2*j+1]);
        float* op = out + (size_t)(i0 + row0 + i) * Wd + n0 + col0;
        #pragma unroll
        for (int j = 0; j < 8; j++) op[j] = c[j] + bias[n0 + col0 + j];
    }
}

// ---------------------------------------------------------------------------
// Kernel 2: softmax stats via streaming QK^T (nothing stored but (m, 1/s)).
// grid(8, 48), block(256). Online (max,sumexp) per thread, shfl-combined.
// ---------------------------------------------------------------------------
__global__ __launch_bounds__(256)
void stats_kernel(const int* __restrict__ mask) {
    __shared__ float As[16][132], Bs[16][68];
    const int z = blockIdx.y;
    const int b = z / Hh;
    const int h = z - b * Hh;
    const int i0 = blockIdx.x * 128;
    const int t = threadIdx.x;
    const int row0 = (t >> 4) * 8;
    const int col0 = (t & 15) * 4;

    const float* Qp = g_q + ((size_t)b * Sq + i0) * Wd + h * Dd;
    const float* Kb = g_k + (size_t)b * Sq * Wd + h * Dd;

    float m[8], s[8];
    #pragma unroll
    for (int i = 0; i < 8; i++) { m[i] = -3.4e38f; s[i] = 0.f; }

    for (int j0 = 0; j0 < Sq; j0 += 64) {
        unsigned long long acc[8][2];
        #pragma unroll
        for (int i = 0; i < 8; i++) { acc[i][0] = 0ull; acc[i][1] = 0ull; }
        gemm_s_tile(Qp, Wd, Kb + (size_t)j0 * Wd, Wd, acc, As, Bs);

        const int4 mk = *(const int4*)(mask + b * Sq + j0 + col0);
        #pragma unroll
        for (int i = 0; i < 8; i++) {
            float v[4];
            unpack2(acc[i][0], v[0], v[1]);
            unpack2(acc[i][1], v[2], v[3]);
            v[0] = (mk.x == 0) ? -1e9f : v[0] * 0.125f;
            v[1] = (mk.y == 0) ? -1e9f : v[1] * 0.125f;
            v[2] = (mk.z == 0) ? -1e9f : v[2] * 0.125f;
            v[3] = (mk.w == 0) ? -1e9f : v[3] * 0.125f;
            float tm = fmaxf(fmaxf(v[0], v[1]), fmaxf(v[2], v[3]));
            float nm = fmaxf(m[i], tm);
            float e = __expf(v[0]-nm) + __expf(v[1]-nm) + __expf(v[2]-nm) + __expf(v[3]-nm);
            s[i] = s[i] * __expf(m[i] - nm) + e;
            m[i] = nm;
        }
    }

    // combine across the 16 threads (tc) owning each row
    #pragma unroll
    for (int i = 0; i < 8; i++) {
        float mm = m[i], ss = s[i];
        #pragma unroll
        for (int off = 1; off < 16; off <<= 1) {
            float mo = __shfl_xor_sync(0xffffffffu, mm, off, 16);
            float so = __shfl_xor_sync(0xffffffffu, ss, off, 16);
            float nm = fmaxf(mm, mo);
            ss = ss * __expf(mm - nm) + so * __expf(mo - nm);
            mm = nm;
        }
        if ((t & 15) == 0) {
            const int r = i0 + row0 + i;
            g_rm[z * Sq + r] = mm;
            g_ri[z * Sq + r] = 1.0f / ss;
        }
    }
}

// ---------------------------------------------------------------------------
// Kernel 3: recompute scores, normalize, write weights ONCE, fused AV.
// grid(8, 48), block(256).
// ---------------------------------------------------------------------------
__global__ __launch_bounds__(256, 2)
void av_kernel(const int* __restrict__ mask, float* __restrict__ attn_out) {
    __shared__ float As[16][132], Bs[16][68];
    __shared__ float Ps[64][132];          // P slice: [k-local][row]
    __shared__ float sm[128], si[128];
    float* attnW = attn_out ? attn_out : g_attn_fallback;

    const int z = blockIdx.y;
    const int b = z / Hh;
    const int h = z - b * Hh;
    const int i0 = blockIdx.x * 128;
    const int t = threadIdx.x;
    const int row0 = (t >> 4) * 8;
    const int col0 = (t & 15) * 4;

    if (t < 128) {
        sm[t] = g_rm[z * Sq + i0 + t];
        si[t] = g_ri[z * Sq + i0 + t];
    }
    __syncthreads();

    const float* Qp = g_q + ((size_t)b * Sq + i0) * Wd + h * Dd;
    const float* Kb = g_k + (size_t)b * Sq * Wd + h * Dd;
    const float* Vb = g_v + (size_t)b * Sq * Wd + h * Dd;

    unsigned long long accv[8][2];
    #pragma unroll
    for (int i = 0; i < 8; i++) { accv[i][0] = 0ull; accv[i][1] = 0ull; }

    for (int j0 = 0; j0 < Sq; j0 += 64) {
        // --- recompute 128x64 score tile ---
        unsigned long long acc[8][2];
        #pragma unroll
        for (int i = 0; i < 8; i++) { acc[i][0] = 0ull; acc[i][1] = 0ull; }
        gemm_s_tile(Qp, Wd, Kb + (size_t)j0 * Wd, Wd, acc, As, Bs);

        // --- normalize to weights; write to gmem (the attn output) ---
        const int4 mk = *(const int4*)(mask + b * Sq + j0 + col0);
        float pv[8][4];
        #pragma unroll
        for (int i = 0; i < 8; i++) {
            float v[4];
            unpack2(acc[i][0], v[0], v[1]);
            unpack2(acc[i][1], v[2], v[3]);
            v[0] = (mk.x == 0) ? -1e9f : v[0] * 0.125f;
            v[1] = (mk.y == 0) ? -1e9f : v[1] * 0.125f;
            v[2] = (mk.z == 0) ? -1e9f : v[2] * 0.125f;
            v[3] = (mk.w == 0) ? -1e9f : v[3] * 0.125f;
            const int r = row0 + i;
            const float mr = sm[r], ir = si[r];
            pv[i][0] = __expf(v[0] - mr) * ir;
            pv[i][1] = __expf(v[1] - mr) * ir;
            pv[i][2] = __expf(v[2] - mr) * ir;
            pv[i][3] = __expf(v[3] - mr) * ir;
            float* op = attnW + ((size_t)z * Sq + i0 + r) * Sq + j0 + col0;
            *(float4*)op = make_float4(pv[i][0], pv[i][1], pv[i][2], pv[i][3]);
        }
        // --- stage P transposed into smem: Ps[k][row] ---
        #pragma unroll
        for (int j = 0; j < 4; j++) {
            *(float4*)&Ps[col0 + j][row0]     = make_float4(pv[0][j], pv[1][j], pv[2][j], pv[3][j]);
            *(float4*)&Ps[col0 + j][row0 + 4] = make_float4(pv[4][j], pv[5][j], pv[6][j], pv[7][j]);
        }
        __syncthreads();

        // --- AV partial: ctx += P[128,64] @ V[64,64] ---
        const int vr = t >> 4;            // 0..15
        const int vc = (t & 15) * 4;
        for (int ks = 0; ks < 4; ks++) {
            *(float4*)&Bs[vr][vc] = *(const float4*)(Vb + (size_t)(j0 + ks * 16 + vr) * Wd + vc);
            __syncthreads();
            #pragma unroll
            for (int kk = 0; kk < 16; kk++) {
                const int kl = ks * 16 + kk;
                float4 x0 = *(const float4*)&Ps[kl][row0];
                float4 x1 = *(const float4*)&Ps[kl][row0 + 4];
                float4 y  = *(const float4*)&Bs[kk][col0];
                unsigned long long bp0 = pack2(y.x, y.y);
                unsigned long long bp1 = pack2(y.z, y.w);
                float av[8] = { x0.x, x0.y, x0.z, x0.w, x1.x, x1.y, x1.z, x1.w };
                #pragma unroll
                for (int i = 0; i < 8; i++) {
                    unsigned long long ap = pack2(av[i], av[i]);
                    accv[i][0] = ffma2(ap, bp0, accv[i][0]);
                    accv[i][1] = ffma2(ap, bp1, accv[i][1]);
                }
            }
            __syncthreads();
        }
    }

    #pragma unroll
    for (int i = 0; i < 8; i++) {
        float c0, c1, c2, c3;
        unpack2(accv[i][0], c0, c1);
        unpack2(accv[i][1], c2, c3);
        float* op = g_ctx + ((size_t)b * Sq + i0 + row0 + i) * Wd + h * Dd + col0;
        *(float4*)op = make_float4(c0, c1, c2, c3);
    }
}

// ---------------------------------------------------------------------------
// Kernel 4: output projection. grid(6, 32), block(256).
// ---------------------------------------------------------------------------
__global__ __launch_bounds__(256)
void oproj_kernel(const float* __restrict__ ow, const float* __restrict__ ob,
                  float* __restrict__ out) {
    __shared__ float As[16][132], Bs[16][132];
    const int i0 = blockIdx.y * 128;
    const int n0 = blockIdx.x * 128;
    unsigned long long acc[8][4];
    #pragma unroll
    for (int i = 0; i < 8; i++)
        #pragma unroll
        for (int j = 0; j < 4; j++) acc[i][j] = 0ull;

    gemm_nt_128(g_ctx + (size_t)i0 * Wd, Wd, ow + (size_t)n0 * Eq, Eq, Wd, acc, As, Bs);

    const int row0 = (threadIdx.x >> 4) * 8;
    const int col0 = (threadIdx.x & 15) * 8;
    #pragma unroll
    for (int i = 0; i < 8; i++) {
        float c[8];
        #pragma unroll
        for (int j = 0; j < 4; j++) unpack2(acc[i][j], c[2*j], c[2*j+1]);
        float* op = out + (size_t)(i0 + row0 + i) * Wd + n0 + col0;
        #pragma unroll
        for (int j = 0; j < 8; j++) op[j] = c[j] + ob[n0 + col0 + j];
    }
}

// ---------------------------------------------------------------------------
extern "C" void kernel_launch(void* const* d_in, const int* in_sizes, int n_in,
                              void* d_out, int out_size) {
    const float* query = (const float*)d_in[0];
    const int*   mask  = (const int*)d_in[1];
    const float* q_w = (const float*)d_in[2];
    const float* q_b = (const float*)d_in[3];
    const float* k_w = (const float*)d_in[4];
    const float* k_b = (const float*)d_in[5];
    const float* v_w = (const float*)d_in[6];
    const float* v_b = (const float*)d_in[7];
    const float* o_w = (const float*)d_in[8];
    const float* o_b = (const float*)d_in[9];

    float* out = (float*)d_out;
    float* attn = ((long long)out_size >= OUT_ELEMS + ATTN_ELEMS) ? out + OUT_ELEMS : nullptr;

    qkv_kernel<<<dim3(Wd / 128, BSq / 128, 3), 256>>>(query, q_w, q_b, k_w, k_b, v_w, v_b);
    stats_kernel<<<dim3(8, NZ), 256>>>(mask);
    av_kernel<<<dim3(8, NZ), 256>>>(mask, attn);
    oproj_kernel<<<dim3(Wd / 128, BSq / 128), 256>>>(o_w, o_b, out);
}

// round 6
// speedup vs baseline: 1.8797x; 1.8797x over previous
#include <cuda_runtime.h>
#include <cuda_bf16.h>
#include <cstdint>

// Fixed shapes: B=4, S=1024, E=1024, width=768 -> H=12, D=64
#define Bq   4
#define Sq   1024
#define Eq   1024
#define Wd   768
#define Hh   12
#define Dd   64
#define BSq  (Bq*Sq)            // 4096
#define NZ   (Bq*Hh)            // 48
#define OUT_ELEMS   ((long long)BSq*Wd)        // 3,145,728
#define ATTN_ELEMS  ((long long)NZ*Sq*Sq)      // 50,331,648

// ---------------- scratch (device globals; no runtime allocation) ----------
__device__ __align__(16) float g_q[BSq*Wd];
__device__ __align__(16) float g_k[BSq*Wd];
__device__ __align__(16) float g_v[BSq*Wd];
__device__ __align__(16) float g_ctx[BSq*Wd];
__device__ __align__(16) float g_pm[NZ*8*Sq];
__device__ __align__(16) float g_ps[NZ*8*Sq];
__device__ __align__(16) float g_rm[NZ*Sq];
__device__ __align__(16) float g_ri[NZ*Sq];
__device__ __align__(16) float g_attn_fallback[NZ*Sq*Sq];

// ======================= mma/ldmatrix primitives (sm_80+ PTX) ==============
__device__ __forceinline__ void ldsm_x4(uint32_t* r, uint32_t addr) {
    asm volatile("ldmatrix.sync.aligned.m8n8.x4.shared.b16 {%0,%1,%2,%3}, [%4];"
        : "=r"(r[0]), "=r"(r[1]), "=r"(r[2]), "=r"(r[3]) : "r"(addr));
}
__device__ __forceinline__ void mma_bf16(float* c, const uint32_t* a,
                                         uint32_t b0, uint32_t b1) {
    asm volatile("mma.sync.aligned.m16n8k16.row.col.f32.bf16.bf16.f32 "
        "{%0,%1,%2,%3}, {%4,%5,%6,%7}, {%8,%9}, {%0,%1,%2,%3};"
        : "+f"(c[0]), "+f"(c[1]), "+f"(c[2]), "+f"(c[3])
        : "r"(a[0]), "r"(a[1]), "r"(a[2]), "r"(a[3]), "r"(b0), "r"(b1));
}

// ---------------------------------------------------------------------------
// Fill a [128 rows x 16 k] fp32 slab into bf16 hi/lo smem tiles.
// Tile layout: row pitch = 12 uint32 (48 bytes) -> conflict-free ldmatrix.
// ---------------------------------------------------------------------------
__device__ __forceinline__ void fill_bf16_tiles(const float* __restrict__ src, int lds,
                                                uint32_t* __restrict__ hi,
                                                uint32_t* __restrict__ lo, int t) {
    #pragma unroll
    for (int u = 0; u < 4; u++) {
        const int p = t + u * 256;        // 0..1023
        const int row = p >> 3;           // 0..127
        const int kp = p & 7;             // float2 index 0..7
        float2 v = *(const float2*)(src + (size_t)row * lds + kp * 2);
        __nv_bfloat16 h0 = __float2bfloat16(v.x);
        __nv_bfloat16 h1 = __float2bfloat16(v.y);
        __nv_bfloat16 l0 = __float2bfloat16(v.x - __bfloat162float(h0));
        __nv_bfloat16 l1 = __float2bfloat16(v.y - __bfloat162float(h1));
        hi[row * 12 + kp] = (uint32_t)__bfloat16_as_ushort(h0) |
                            ((uint32_t)__bfloat16_as_ushort(h1) << 16);
        lo[row * 12 + kp] = (uint32_t)__bfloat16_as_ushort(l0) |
                            ((uint32_t)__bfloat16_as_ushort(l1) << 16);
    }
}

// ---------------------------------------------------------------------------
// HMMA projection GEMM: out[i0:i0+128, n0:n0+128] = A[128,768] @ W^T + bias
// bf16x3 split, fp32 accumulate. 256 threads, warp tile 32x64.
// mode 0: A=Ain (lda), W/bias/out selected by blockIdx.z (q/k/v)
// mode 1: A=g_ctx (lda=768), W0/b0 -> out_ext
// ---------------------------------------------------------------------------
__global__ __launch_bounds__(256)
void proj_mma(int mode, const float* __restrict__ Ain, int lda,
              const float* __restrict__ W0, const float* __restrict__ b0,
              const float* __restrict__ W1, const float* __restrict__ b1,
              const float* __restrict__ W2, const float* __restrict__ b2,
              float* __restrict__ out_ext) {
    __shared__ uint32_t Ah[128*12], Al[128*12], Bh[128*12], Bl[128*12];

    const int t = threadIdx.x;
    const int wid = t >> 5;
    const int lane = t & 31;

    const float* A; const float* W; const float* bias; float* out;
    if (mode == 1) { A = g_ctx; W = W0; bias = b0; out = out_ext; }
    else {
        A = Ain;
        if (blockIdx.z == 0)      { W = W0; bias = b0; out = g_q; }
        else if (blockIdx.z == 1) { W = W1; bias = b1; out = g_k; }
        else                      { W = W2; bias = b2; out = g_v; }
    }

    const int n0 = blockIdx.x * 128;
    const int i0 = blockIdx.y * 128;
    const int wm = (wid & 3) * 32;     // warp m offset in tile
    const int wn = (wid >> 2) * 64;    // warp n offset in tile

    const float* Asrc = A + (size_t)i0 * lda;
    const float* Wsrc = W + (size_t)n0 * Eq;

    float acc[2][8][4];
    #pragma unroll
    for (int mi = 0; mi < 2; mi++)
        #pragma unroll
        for (int ni = 0; ni < 8; ni++)
            #pragma unroll
            for (int j = 0; j < 4; j++) acc[mi][ni][j] = 0.f;

    // ldmatrix source addresses (row pitch 48B, k-half offset 16B)
    const uint32_t a_base = (uint32_t)__cvta_generic_to_shared(Ah);
    const uint32_t al_base = (uint32_t)__cvta_generic_to_shared(Al);
    const uint32_t b_base = (uint32_t)__cvta_generic_to_shared(Bh);
    const uint32_t bl_base = (uint32_t)__cvta_generic_to_shared(Bl);
    const int frag_row = ((lane >> 3) & 1) * 8 + (lane & 7);
    const int frag_koff = (lane >> 4) * 16;              // A: k-half by lane/16
    const int bfrag_row = ((lane >> 4) & 1) * 8 + (lane & 7);
    const int bfrag_koff = ((lane >> 3) & 1) * 16;       // B: k-half by (lane/8)&1

    for (int c = 0; c < 48; c++) {
        const int k0 = c * 16;
        __syncthreads();
        fill_bf16_tiles(Asrc + k0, lda, Ah, Al, t);
        fill_bf16_tiles(Wsrc + k0, Eq, Bh, Bl, t);
        __syncthreads();

        uint32_t ah[2][4], alr[2][4];
        #pragma unroll
        for (int mi = 0; mi < 2; mi++) {
            const uint32_t off = (uint32_t)((wm + mi * 16 + frag_row) * 48 + frag_koff);
            ldsm_x4(ah[mi], a_base + off);
            ldsm_x4(alr[mi], al_base + off);
        }
        #pragma unroll
        for (int g = 0; g < 4; g++) {
            uint32_t bh[4], blr[4];
            const uint32_t off = (uint32_t)((wn + g * 16 + bfrag_row) * 48 + bfrag_koff);
            ldsm_x4(bh, b_base + off);
            ldsm_x4(blr, bl_base + off);
            #pragma unroll
            for (int s = 0; s < 2; s++) {
                #pragma unroll
                for (int mi = 0; mi < 2; mi++) {
                    float* cc = acc[mi][g * 2 + s];
                    mma_bf16(cc, ah[mi],  bh[2*s],  bh[2*s+1]);   // Ah*Bh
                    mma_bf16(cc, ah[mi],  blr[2*s], blr[2*s+1]);  // Ah*Bl
                    mma_bf16(cc, alr[mi], bh[2*s],  bh[2*s+1]);   // Al*Bh
                }
            }
        }
    }

    // Epilogue: C frag c0,c1 = (row, col..col+1), c2,c3 = (row+8, col..col+1)
    #pragma unroll
    for (int mi = 0; mi < 2; mi++) {
        #pragma unroll
        for (int ni = 0; ni < 8; ni++) {
            const int row = i0 + wm + mi * 16 + (lane >> 2);
            const int col = n0 + wn + ni * 8 + (lane & 3) * 2;
            float2 bb = *(const float2*)(bias + col);
            float2 v0 = make_float2(acc[mi][ni][0] + bb.x, acc[mi][ni][1] + bb.y);
            float2 v1 = make_float2(acc[mi][ni][2] + bb.x, acc[mi][ni][3] + bb.y);
            *(float2*)(out + (size_t)row * Wd + col) = v0;
            *(float2*)(out + (size_t)(row + 8) * Wd + col) = v1;
        }
    }
}

// ======================= fp32 attention middle (R3, measured best) =========
__device__ __forceinline__ unsigned long long pack2(float x, float y) {
    unsigned long long r;
    asm("mov.b64 %0, {%1, %2};" : "=l"(r) : "f"(x), "f"(y));
    return r;
}
__device__ __forceinline__ void unpack2(unsigned long long v, float& x, float& y) {
    asm("mov.b64 {%0, %1}, %2;" : "=f"(x), "=f"(y) : "l"(v));
}
__device__ __forceinline__ unsigned long long ffma2(unsigned long long a,
                                                    unsigned long long b,
                                                    unsigned long long c) {
    unsigned long long d;
    asm("fma.rn.f32x2 %0, %1, %2, %3;" : "=l"(d) : "l"(a), "l"(b), "l"(c));
    return d;
}

__device__ __forceinline__ void gemm_nt_128(const float* __restrict__ A, int lda,
                                            const float* __restrict__ B, int ldb,
                                            int K, unsigned long long (&acc)[8][4],
                                            float (&As)[16][132], float (&Bs)[16][132]) {
    const int t  = threadIdx.x;
    const int tr = t >> 4;
    const int tc = t & 15;
    const int lr = t >> 2;
    const int lk = (t & 3) << 2;

    for (int k0 = 0; k0 < K; k0 += 16) {
        float4 a0 = *(const float4*)(A + (size_t)lr * lda + k0 + lk);
        float4 a1 = *(const float4*)(A + (size_t)(lr + 64) * lda + k0 + lk);
        float4 b0 = *(const float4*)(B + (size_t)lr * ldb + k0 + lk);
        float4 b1 = *(const float4*)(B + (size_t)(lr + 64) * ldb + k0 + lk);
        As[lk+0][lr] = a0.x; As[lk+1][lr] = a0.y; As[lk+2][lr] = a0.z; As[lk+3][lr] = a0.w;
        As[lk+0][lr+64] = a1.x; As[lk+1][lr+64] = a1.y; As[lk+2][lr+64] = a1.z; As[lk+3][lr+64] = a1.w;
        Bs[lk+0][lr] = b0.x; Bs[lk+1][lr] = b0.y; Bs[lk+2][lr] = b0.z; Bs[lk+3][lr] = b0.w;
        Bs[lk+0][lr+64] = b1.x; Bs[lk+1][lr+64] = b1.y; Bs[lk+2][lr+64] = b1.z; Bs[lk+3][lr+64] = b1.w;
        __syncthreads();

        #pragma unroll
        for (int kk = 0; kk < 16; kk++) {
            float4 x0 = *(const float4*)&As[kk][tr * 8];
            float4 x1 = *(const float4*)&As[kk][tr * 8 + 4];
            float4 y0 = *(const float4*)&Bs[kk][tc * 8];
            float4 y1 = *(const float4*)&Bs[kk][tc * 8 + 4];
            unsigned long long bp[4] = { pack2(y0.x, y0.y), pack2(y0.z, y0.w),
                                         pack2(y1.x, y1.y), pack2(y1.z, y1.w) };
            float av[8] = { x0.x, x0.y, x0.z, x0.w, x1.x, x1.y, x1.z, x1.w };
            #pragma unroll
            for (int i = 0; i < 8; i++) {
                unsigned long long ap = pack2(av[i], av[i]);
                #pragma unroll
                for (int j = 0; j < 4; j++)
                    acc[i][j] = ffma2(ap, bp[j], acc[i][j]);
            }
        }
        __syncthreads();
    }
}

__global__ __launch_bounds__(256)
void score_kernel(const int* __restrict__ mask, float* __restrict__ attn_out) {
    __shared__ float As[16][132], Bs[16][132];
    __shared__ int smask[128];
    float* attnW = attn_out ? attn_out : g_attn_fallback;

    const int z = blockIdx.z;
    const int b = z / Hh;
    const int h = z - b * Hh;
    const int i0 = blockIdx.y * 128;
    const int j0 = blockIdx.x * 128;
    const int cb = blockIdx.x;

    if (threadIdx.x < 128) smask[threadIdx.x] = mask[b * Sq + j0 + threadIdx.x];

    const float* Qp = g_q + ((size_t)b * Sq + i0) * Wd + h * Dd;
    const float* Kp = g_k + ((size_t)b * Sq + j0) * Wd + h * Dd;

    unsigned long long acc[8][4];
    #pragma unroll
    for (int i = 0; i < 8; i++)
        #pragma unroll
        for (int j = 0; j < 4; j++) acc[i][j] = 0ull;

    gemm_nt_128(Qp, Wd, Kp, Wd, Dd, acc, As, Bs);

    const int tr = threadIdx.x >> 4, tc = threadIdx.x & 15;
    const int row0 = tr * 8, col0 = tc * 8;

    #pragma unroll
    for (int i = 0; i < 8; i++) {
        const int r = i0 + row0 + i;
        float v[8];
        #pragma unroll
        for (int j = 0; j < 4; j++) unpack2(acc[i][j], v[2*j], v[2*j+1]);
        #pragma unroll
        for (int j = 0; j < 8; j++) {
            float x = v[j] * 0.125f;
            if (smask[col0 + j] == 0) x = -1e9f;
            v[j] = x;
        }
        float* op = attnW + ((size_t)z * Sq + r) * Sq + j0 + col0;
        *(float4*)&op[0] = make_float4(v[0], v[1], v[2], v[3]);
        *(float4*)&op[4] = make_float4(v[4], v[5], v[6], v[7]);

        float m = v[0];
        #pragma unroll
        for (int j = 1; j < 8; j++) m = fmaxf(m, v[j]);
        #pragma unroll
        for (int o = 1; o < 16; o <<= 1)
            m = fmaxf(m, __shfl_xor_sync(0xffffffffu, m, o));
        float s = 0.f;
        #pragma unroll
        for (int j = 0; j < 8; j++) s += __expf(v[j] - m);
        #pragma unroll
        for (int o = 1; o < 16; o <<= 1)
            s += __shfl_xor_sync(0xffffffffu, s, o);
        if (tc == 0) {
            g_pm[((size_t)z * 8 + cb) * Sq + r] = m;
            g_ps[((size_t)z * 8 + cb) * Sq + r] = s;
        }
    }
}

__global__ __launch_bounds__(256)
void combine_kernel() {
    const int idx = blockIdx.x * 256 + threadIdx.x;
    const int z = idx >> 10, r = idx & 1023;
    float m = -3.4e38f;
    float pm[8], ps[8];
    #pragma unroll
    for (int cb = 0; cb < 8; cb++) {
        pm[cb] = g_pm[((size_t)z * 8 + cb) * Sq + r];
        ps[cb] = g_ps[((size_t)z * 8 + cb) * Sq + r];
        m = fmaxf(m, pm[cb]);
    }
    float s = 0.f;
    #pragma unroll
    for (int cb = 0; cb < 8; cb++) s += ps[cb] * __expf(pm[cb] - m);
    g_rm[idx] = m;
    g_ri[idx] = 1.0f / s;
}

__global__ __launch_bounds__(256)
void av_kernel(float* __restrict__ attn_out) {
    __shared__ float As[16][132], Bs[16][72];
    __shared__ float sm[128], si[128];
    float* attnW = attn_out ? attn_out : g_attn_fallback;

    const int z = blockIdx.y;
    const int b = z / Hh;
    const int h = z - b * Hh;
    const int i0 = blockIdx.x * 128;
    const int t = threadIdx.x;

    if (t < 128) {
        sm[t] = g_rm[z * Sq + i0 + t];
        si[t] = g_ri[z * Sq + i0 + t];
    }
    __syncthreads();

    float* Arow = attnW + ((size_t)z * Sq + i0) * Sq;
    const float* Vp = g_v + (size_t)b * Sq * Wd + h * Dd;

    const int tr = t >> 4, tc = t & 15;
    const int row0 = tr * 8, col0 = tc * 4;
    const int lr = t >> 2, lk = (t & 3) << 2;
    const int vk = t >> 4, vn = (t & 15) << 2;

    unsigned long long acc[8][2];
    #pragma unroll
    for (int i = 0; i < 8; i++) { acc[i][0] = 0ull; acc[i][1] = 0ull; }

    for (int k0 = 0; k0 < Sq; k0 += 16) {
        #pragma unroll
        for (int half = 0; half < 2; half++) {
            const int r = lr + half * 64;
            float* ap = Arow + (size_t)r * Sq + k0 + lk;
            float4 v4 = *(const float4*)ap;
            const float mr = sm[r], ir = si[r];
            float4 p;
            p.x = __expf(v4.x - mr) * ir;
            p.y = __expf(v4.y - mr) * ir;
            p.z = __expf(v4.z - mr) * ir;
            p.w = __expf(v4.w - mr) * ir;
            As[lk+0][r] = p.x; As[lk+1][r] = p.y; As[lk+2][r] = p.z; As[lk+3][r] = p.w;
            *(float4*)ap = p;
        }
        float4 w4 = *(const float4*)(Vp + (size_t)(k0 + vk) * Wd + vn);
        *(float4*)&Bs[vk][vn] = w4;
        __syncthreads();

        #pragma unroll
        for (int kk = 0; kk < 16; kk++) {
            float4 x0 = *(const float4*)&As[kk][row0];
            float4 x1 = *(const float4*)&As[kk][row0 + 4];
            float4 y  = *(const float4*)&Bs[kk][col0];
            unsigned long long bp0 = pack2(y.x, y.y);
            unsigned long long bp1 = pack2(y.z, y.w);
            float av[8] = { x0.x, x0.y, x0.z, x0.w, x1.x, x1.y, x1.z, x1.w };
            #pragma unroll
            for (int i = 0; i < 8; i++) {
                unsigned long long ap = pack2(av[i], av[i]);
                acc[i][0] = ffma2(ap, bp0, acc[i][0]);
                acc[i][1] = ffma2(ap, bp1, acc[i][1]);
            }
        }
        __syncthreads();
    }

    #pragma unroll
    for (int i = 0; i < 8; i++) {
        float c0, c1, c2, c3;
        unpack2(acc[i][0], c0, c1);
        unpack2(acc[i][1], c2, c3);
        float* op = g_ctx + ((size_t)b * Sq + i0 + row0 + i) * Wd + h * Dd + col0;
        *(float4*)op = make_float4(c0, c1, c2, c3);
    }
}

// ---------------------------------------------------------------------------
extern "C" void kernel_launch(void* const* d_in, const int* in_sizes, int n_in,
                              void* d_out, int out_size) {
    const float* query = (const float*)d_in[0];
    const int*   mask  = (const int*)d_in[1];
    const float* q_w = (const float*)d_in[2];
    const float* q_b = (const float*)d_in[3];
    const float* k_w = (const float*)d_in[4];
    const float* k_b = (const float*)d_in[5];
    const float* v_w = (const float*)d_in[6];
    const float* v_b = (const float*)d_in[7];
    const float* o_w = (const float*)d_in[8];
    const float* o_b = (const float*)d_in[9];

    float* out = (float*)d_out;
    float* attn = ((long long)out_size >= OUT_ELEMS + ATTN_ELEMS) ? out + OUT_ELEMS : nullptr;

    proj_mma<<<dim3(6, 32, 3), 256>>>(0, query, Eq,
                                      q_w, q_b, k_w, k_b, v_w, v_b, nullptr);
    score_kernel<<<dim3(8, 8, NZ), 256>>>(mask, attn);
    combine_kernel<<<dim3(NZ * Sq / 256), 256>>>();
    av_kernel<<<dim3(8, NZ), 256>>>(attn);
    proj_mma<<<dim3(6, 32, 1), 256>>>(1, nullptr, Wd,
                                      o_w, o_b, nullptr, nullptr, nullptr, nullptr, out);
}

// round 7
// speedup vs baseline: 1.8844x; 1.0025x over previous
#include <cuda_runtime.h>
#include <cuda_bf16.h>
#include <cstdint>

// Fixed shapes: B=4, S=1024, E=1024, width=768 -> H=12, D=64
#define Bq   4
#define Sq   1024
#define Eq   1024
#define Wd   768
#define Hh   12
#define Dd   64
#define BSq  (Bq*Sq)            // 4096
#define NZ   (Bq*Hh)            // 48
#define OUT_ELEMS   ((long long)BSq*Wd)        // 3,145,728
#define ATTN_ELEMS  ((long long)NZ*Sq*Sq)      // 50,331,648

// ---------------- scratch (device globals; no runtime allocation) ----------
__device__ __align__(16) float g_q[BSq*Wd];
__device__ __align__(16) float g_k[BSq*Wd];
__device__ __align__(16) float g_v[BSq*Wd];
__device__ __align__(16) float g_ctx[BSq*Wd];
__device__ __align__(16) float g_rm[NZ*Sq];
__device__ __align__(16) float g_ri[NZ*Sq];
__device__ __align__(16) float g_attn_fallback[NZ*Sq*Sq];

// ======================= mma/ldmatrix primitives (sm_80+ PTX) ==============
__device__ __forceinline__ void ldsm_x4(uint32_t* r, uint32_t addr) {
    asm volatile("ldmatrix.sync.aligned.m8n8.x4.shared.b16 {%0,%1,%2,%3}, [%4];"
        : "=r"(r[0]), "=r"(r[1]), "=r"(r[2]), "=r"(r[3]) : "r"(addr));
}
__device__ __forceinline__ void mma_bf16(float* c, const uint32_t* a,
                                         uint32_t b0, uint32_t b1) {
    asm volatile("mma.sync.aligned.m16n8k16.row.col.f32.bf16.bf16.f32 "
        "{%0,%1,%2,%3}, {%4,%5,%6,%7}, {%8,%9}, {%0,%1,%2,%3};"
        : "+f"(c[0]), "+f"(c[1]), "+f"(c[2]), "+f"(c[3])
        : "r"(a[0]), "r"(a[1]), "r"(a[2]), "r"(a[3]), "r"(b0), "r"(b1));
}
__device__ __forceinline__ uint32_t packbf(float x, float y) {
    __nv_bfloat162 h = __floats2bfloat162_rn(x, y);
    return *(uint32_t*)&h;
}

// ===========================================================================
// proj_mma: unchanged from R6 (measured good)
// ===========================================================================
__device__ __forceinline__ void fill_bf16_tiles(const float* __restrict__ src, int lds,
                                                uint32_t* __restrict__ hi,
                                                uint32_t* __restrict__ lo, int t) {
    #pragma unroll
    for (int u = 0; u < 4; u++) {
        const int p = t + u * 256;
        const int row = p >> 3;
        const int kp = p & 7;
        float2 v = *(const float2*)(src + (size_t)row * lds + kp * 2);
        __nv_bfloat16 h0 = __float2bfloat16(v.x);
        __nv_bfloat16 h1 = __float2bfloat16(v.y);
        __nv_bfloat16 l0 = __float2bfloat16(v.x - __bfloat162float(h0));
        __nv_bfloat16 l1 = __float2bfloat16(v.y - __bfloat162float(h1));
        hi[row * 12 + kp] = (uint32_t)__bfloat16_as_ushort(h0) |
                            ((uint32_t)__bfloat16_as_ushort(h1) << 16);
        lo[row * 12 + kp] = (uint32_t)__bfloat16_as_ushort(l0) |
                            ((uint32_t)__bfloat16_as_ushort(l1) << 16);
    }
}

__global__ __launch_bounds__(256)
void proj_mma(int mode, const float* __restrict__ Ain, int lda,
              const float* __restrict__ W0, const float* __restrict__ b0,
              const float* __restrict__ W1, const float* __restrict__ b1,
              const float* __restrict__ W2, const float* __restrict__ b2,
              float* __restrict__ out_ext) {
    __shared__ uint32_t Ah[128*12], Al[128*12], Bh[128*12], Bl[128*12];

    const int t = threadIdx.x;
    const int wid = t >> 5;
    const int lane = t & 31;

    const float* A; const float* W; const float* bias; float* out;
    if (mode == 1) { A = g_ctx; W = W0; bias = b0; out = out_ext; }
    else {
        A = Ain;
        if (blockIdx.z == 0)      { W = W0; bias = b0; out = g_q; }
        else if (blockIdx.z == 1) { W = W1; bias = b1; out = g_k; }
        else                      { W = W2; bias = b2; out = g_v; }
    }

    const int n0 = blockIdx.x * 128;
    const int i0 = blockIdx.y * 128;
    const int wm = (wid & 3) * 32;
    const int wn = (wid >> 2) * 64;

    const float* Asrc = A + (size_t)i0 * lda;
    const float* Wsrc = W + (size_t)n0 * Eq;

    float acc[2][8][4];
    #pragma unroll
    for (int mi = 0; mi < 2; mi++)
        #pragma unroll
        for (int ni = 0; ni < 8; ni++)
            #pragma unroll
            for (int j = 0; j < 4; j++) acc[mi][ni][j] = 0.f;

    const uint32_t a_base = (uint32_t)__cvta_generic_to_shared(Ah);
    const uint32_t al_base = (uint32_t)__cvta_generic_to_shared(Al);
    const uint32_t b_base = (uint32_t)__cvta_generic_to_shared(Bh);
    const uint32_t bl_base = (uint32_t)__cvta_generic_to_shared(Bl);
    const int frag_row = ((lane >> 3) & 1) * 8 + (lane & 7);
    const int frag_koff = (lane >> 4) * 16;
    const int bfrag_row = ((lane >> 4) & 1) * 8 + (lane & 7);
    const int bfrag_koff = ((lane >> 3) & 1) * 16;

    for (int c = 0; c < 48; c++) {
        const int k0 = c * 16;
        __syncthreads();
        fill_bf16_tiles(Asrc + k0, lda, Ah, Al, t);
        fill_bf16_tiles(Wsrc + k0, Eq, Bh, Bl, t);
        __syncthreads();

        uint32_t ah[2][4], alr[2][4];
        #pragma unroll
        for (int mi = 0; mi < 2; mi++) {
            const uint32_t off = (uint32_t)((wm + mi * 16 + frag_row) * 48 + frag_koff);
            ldsm_x4(ah[mi], a_base + off);
            ldsm_x4(alr[mi], al_base + off);
        }
        #pragma unroll
        for (int g = 0; g < 4; g++) {
            uint32_t bh[4], blr[4];
            const uint32_t off = (uint32_t)((wn + g * 16 + bfrag_row) * 48 + bfrag_koff);
            ldsm_x4(bh, b_base + off);
            ldsm_x4(blr, bl_base + off);
            #pragma unroll
            for (int s = 0; s < 2; s++) {
                #pragma unroll
                for (int mi = 0; mi < 2; mi++) {
                    float* cc = acc[mi][g * 2 + s];
                    mma_bf16(cc, ah[mi],  bh[2*s],  bh[2*s+1]);
                    mma_bf16(cc, ah[mi],  blr[2*s], blr[2*s+1]);
                    mma_bf16(cc, alr[mi], bh[2*s],  bh[2*s+1]);
                }
            }
        }
    }

    #pragma unroll
    for (int mi = 0; mi < 2; mi++) {
        #pragma unroll
        for (int ni = 0; ni < 8; ni++) {
            const int row = i0 + wm + mi * 16 + (lane >> 2);
            const int col = n0 + wn + ni * 8 + (lane & 3) * 2;
            float2 bb = *(const float2*)(bias + col);
            float2 v0 = make_float2(acc[mi][ni][0] + bb.x, acc[mi][ni][1] + bb.y);
            float2 v1 = make_float2(acc[mi][ni][2] + bb.x, acc[mi][ni][3] + bb.y);
            *(float2*)(out + (size_t)row * Wd + col) = v0;
            *(float2*)(out + (size_t)(row + 8) * Wd + col) = v1;
        }
    }
}

// ===========================================================================
// Shared tile converters for attention (pitch = 72 bf16 = 144B, ldmatrix-safe)
// ===========================================================================
#define PITCH 72
__device__ __forceinline__ void fill_qtile(const float* __restrict__ src,
                                           ushort* __restrict__ hi,
                                           ushort* __restrict__ lo, int t, int rows) {
    const int units = rows * 32;                 // float2 units (64 cols)
    for (int p = t; p < units; p += 256) {
        const int row = p >> 5;
        const int f2 = p & 31;
        float2 v = *(const float2*)(src + (size_t)row * Wd + f2 * 2);
        __nv_bfloat16 h0 = __float2bfloat16(v.x);
        __nv_bfloat16 h1 = __float2bfloat16(v.y);
        __nv_bfloat16 l0 = __float2bfloat16(v.x - __bfloat162float(h0));
        __nv_bfloat16 l1 = __float2bfloat16(v.y - __bfloat162float(h1));
        *(uint32_t*)(hi + row * PITCH + f2 * 2) =
            (uint32_t)__bfloat16_as_ushort(h0) | ((uint32_t)__bfloat16_as_ushort(h1) << 16);
        *(uint32_t*)(lo + row * PITCH + f2 * 2) =
            (uint32_t)__bfloat16_as_ushort(l0) | ((uint32_t)__bfloat16_as_ushort(l1) << 16);
    }
}
// V^T tile: read V[key][d] (64x64), store transposed [d][key]
__device__ __forceinline__ void fill_vt(const float* __restrict__ src,
                                        ushort* __restrict__ hi,
                                        ushort* __restrict__ lo, int t) {
    #pragma unroll
    for (int u = 0; u < 4; u++) {
        const int p = t + u * 256;               // 0..1023
        const int key = p >> 4;
        const int d4 = p & 15;
        float4 v = *(const float4*)(src + (size_t)key * Wd + d4 * 4);
        float vv[4] = { v.x, v.y, v.z, v.w };
        #pragma unroll
        for (int i = 0; i < 4; i++) {
            const int d = d4 * 4 + i;
            __nv_bfloat16 h = __float2bfloat16(vv[i]);
            __nv_bfloat16 l = __float2bfloat16(vv[i] - __bfloat162float(h));
            hi[d * PITCH + key] = __bfloat16_as_ushort(h);
            lo[d * PITCH + key] = __bfloat16_as_ushort(l);
        }
    }
}

// ===========================================================================
// stats_mma: streaming QK^T (HMMA) -> per-row (max, 1/sum). grid(8, 48), 256.
// smem: QH,QL (128x72) + KH,KL (64x72) = 55296 B (dynamic)
// ===========================================================================
#define STATS_SMEM (2*128*PITCH*2 + 2*64*PITCH*2)
__global__ __launch_bounds__(256)
void stats_mma(const int* __restrict__ mask) {
    extern __shared__ ushort smem_u[];
    ushort* QH = smem_u;
    ushort* QL = QH + 128 * PITCH;
    ushort* KH = QL + 128 * PITCH;
    ushort* KL = KH + 64 * PITCH;

    const int t = threadIdx.x;
    const int wid = t >> 5;
    const int lane = t & 31;
    const int z = blockIdx.y;
    const int b = z / Hh;
    const int h = z - b * Hh;
    const int i0 = blockIdx.x * 128;
    const int wm = wid * 16;

    const float* Qsrc = g_q + ((size_t)b * Sq + i0) * Wd + h * Dd;
    const float* Ksrc = g_k + (size_t)b * Sq * Wd + h * Dd;
    const int* mrow = mask + b * Sq;

    fill_qtile(Qsrc, QH, QL, t, 128);
    __syncthreads();

    const uint32_t qh_base = (uint32_t)__cvta_generic_to_shared(QH);
    const uint32_t ql_base = (uint32_t)__cvta_generic_to_shared(QL);
    const uint32_t kh_base = (uint32_t)__cvta_generic_to_shared(KH);
    const uint32_t kl_base = (uint32_t)__cvta_generic_to_shared(KL);
    const int frag_row = ((lane >> 3) & 1) * 8 + (lane & 7);
    const int frag_koff = (lane >> 4) * 16;
    const int bfrag_row = ((lane >> 4) & 1) * 8 + (lane & 7);
    const int bfrag_koff = ((lane >> 3) & 1) * 16;

    uint32_t qh[4][4], ql[4][4];
    #pragma unroll
    for (int kb = 0; kb < 4; kb++) {
        const uint32_t off = (uint32_t)((wm + frag_row) * (PITCH * 2) + kb * 32 + frag_koff);
        ldsm_x4(qh[kb], qh_base + off);
        ldsm_x4(ql[kb], ql_base + off);
    }

    float m0 = -3.4e38f, s0 = 0.f, m1 = -3.4e38f, s1 = 0.f;

    for (int j0 = 0; j0 < Sq; j0 += 64) {
        __syncthreads();
        fill_qtile(Ksrc + (size_t)j0 * Wd, KH, KL, t, 64);
        __syncthreads();

        #pragma unroll
        for (int p = 0; p < 4; p++) {
            float acc[2][4] = {};
            #pragma unroll
            for (int kb = 0; kb < 4; kb++) {
                uint32_t kh[4], kl[4];
                const uint32_t off = (uint32_t)((p * 16 + bfrag_row) * (PITCH * 2) + kb * 32 + bfrag_koff);
                ldsm_x4(kh, kh_base + off);
                ldsm_x4(kl, kl_base + off);
                #pragma unroll
                for (int s = 0; s < 2; s++) {
                    mma_bf16(acc[s], qh[kb], kh[2*s], kh[2*s+1]);
                    mma_bf16(acc[s], qh[kb], kl[2*s], kl[2*s+1]);
                    mma_bf16(acc[s], ql[kb], kh[2*s], kh[2*s+1]);
                }
            }
            #pragma unroll
            for (int s = 0; s < 2; s++) {
                const int col = j0 + p * 16 + s * 8 + (lane & 3) * 2;
                const int mk0 = __ldg(mrow + col);
                const int mk1 = __ldg(mrow + col + 1);
                float v0 = mk0 ? acc[s][0] * 0.125f : -1e9f;
                float v1 = mk1 ? acc[s][1] * 0.125f : -1e9f;
                float v2 = mk0 ? acc[s][2] * 0.125f : -1e9f;
                float v3 = mk1 ? acc[s][3] * 0.125f : -1e9f;
                float nm0 = fmaxf(m0, fmaxf(v0, v1));
                s0 = s0 * __expf(m0 - nm0) + __expf(v0 - nm0) + __expf(v1 - nm0);
                m0 = nm0;
                float nm1 = fmaxf(m1, fmaxf(v2, v3));
                s1 = s1 * __expf(m1 - nm1) + __expf(v2 - nm1) + __expf(v3 - nm1);
                m1 = nm1;
            }
        }
    }

    // reduce across the 4 lanes of each row quad
    #pragma unroll
    for (int off = 1; off < 4; off <<= 1) {
        float mo = __shfl_xor_sync(0xffffffffu, m0, off);
        float so = __shfl_xor_sync(0xffffffffu, s0, off);
        float nm = fmaxf(m0, mo);
        s0 = s0 * __expf(m0 - nm) + so * __expf(mo - nm);
        m0 = nm;
        mo = __shfl_xor_sync(0xffffffffu, m1, off);
        so = __shfl_xor_sync(0xffffffffu, s1, off);
        nm = fmaxf(m1, mo);
        s1 = s1 * __expf(m1 - nm) + so * __expf(mo - nm);
        m1 = nm;
    }
    if ((lane & 3) == 0) {
        const int r = i0 + wm + (lane >> 2);
        g_rm[z * Sq + r] = m0;
        g_ri[z * Sq + r] = 1.0f / s0;
        g_rm[z * Sq + r + 8] = m1;
        g_ri[z * Sq + r + 8] = 1.0f / s1;
    }
}

// ===========================================================================
// av_mma: recompute QK^T (HMMA), normalize, write P once, fused P@V (HMMA).
// grid(8, 48), 256 threads.
// smem: QH,QL(128x72) + KH,KL(64x72) + VH,VL(64x72) = 73728 B (dynamic)
// ===========================================================================
#define AV_SMEM (2*128*PITCH*2 + 4*64*PITCH*2)
__global__ __launch_bounds__(256)
void av_mma(const int* __restrict__ mask, float* __restrict__ attn_out) {
    extern __shared__ ushort smem_u[];
    ushort* QH = smem_u;
    ushort* QL = QH + 128 * PITCH;
    ushort* KH = QL + 128 * PITCH;
    ushort* KL = KH + 64 * PITCH;
    ushort* VH = KL + 64 * PITCH;
    ushort* VL = VH + 64 * PITCH;

    float* attnW = attn_out ? attn_out : g_attn_fallback;

    const int t = threadIdx.x;
    const int wid = t >> 5;
    const int lane = t & 31;
    const int z = blockIdx.y;
    const int b = z / Hh;
    const int h = z - b * Hh;
    const int i0 = blockIdx.x * 128;
    const int wm = wid * 16;

    const float* Qsrc = g_q + ((size_t)b * Sq + i0) * Wd + h * Dd;
    const float* Ksrc = g_k + (size_t)b * Sq * Wd + h * Dd;
    const float* Vsrc = g_v + (size_t)b * Sq * Wd + h * Dd;
    const int* mrow = mask + b * Sq;

    fill_qtile(Qsrc, QH, QL, t, 128);
    __syncthreads();

    const uint32_t qh_base = (uint32_t)__cvta_generic_to_shared(QH);
    const uint32_t ql_base = (uint32_t)__cvta_generic_to_shared(QL);
    const uint32_t kh_base = (uint32_t)__cvta_generic_to_shared(KH);
    const uint32_t kl_base = (uint32_t)__cvta_generic_to_shared(KL);
    const uint32_t vh_base = (uint32_t)__cvta_generic_to_shared(VH);
    const uint32_t vl_base = (uint32_t)__cvta_generic_to_shared(VL);
    const int frag_row = ((lane >> 3) & 1) * 8 + (lane & 7);
    const int frag_koff = (lane >> 4) * 16;
    const int bfrag_row = ((lane >> 4) & 1) * 8 + (lane & 7);
    const int bfrag_koff = ((lane >> 3) & 1) * 16;

    uint32_t qh[4][4], ql[4][4];
    #pragma unroll
    for (int kb = 0; kb < 4; kb++) {
        const uint32_t off = (uint32_t)((wm + frag_row) * (PITCH * 2) + kb * 32 + frag_koff);
        ldsm_x4(qh[kb], qh_base + off);
        ldsm_x4(ql[kb], ql_base + off);
    }

    // per-thread row stats (rows wm+lane>>2, +8)
    const int r0 = wm + (lane >> 2);
    const float mm0 = g_rm[z * Sq + i0 + r0];
    const float ii0 = g_ri[z * Sq + i0 + r0];
    const float mm1 = g_rm[z * Sq + i0 + r0 + 8];
    const float ii1 = g_ri[z * Sq + i0 + r0 + 8];

    float ctx[8][4];
    #pragma unroll
    for (int ni = 0; ni < 8; ni++)
        #pragma unroll
        for (int j = 0; j < 4; j++) ctx[ni][j] = 0.f;

    float* Prow0 = attnW + ((size_t)z * Sq + i0 + r0) * Sq;
    float* Prow1 = attnW + ((size_t)z * Sq + i0 + r0 + 8) * Sq;

    for (int j0 = 0; j0 < Sq; j0 += 64) {
        __syncthreads();
        fill_qtile(Ksrc + (size_t)j0 * Wd, KH, KL, t, 64);
        fill_vt(Vsrc + (size_t)j0 * Wd, VH, VL, t);
        __syncthreads();

        #pragma unroll
        for (int p = 0; p < 4; p++) {
            // ---- S tile: rows wm..wm+16, keys j0+p*16..+16 ----
            float acc[2][4] = {};
            #pragma unroll
            for (int kb = 0; kb < 4; kb++) {
                uint32_t kh[4], kl[4];
                const uint32_t off = (uint32_t)((p * 16 + bfrag_row) * (PITCH * 2) + kb * 32 + bfrag_koff);
                ldsm_x4(kh, kh_base + off);
                ldsm_x4(kl, kl_base + off);
                #pragma unroll
                for (int s = 0; s < 2; s++) {
                    mma_bf16(acc[s], qh[kb], kh[2*s], kh[2*s+1]);
                    mma_bf16(acc[s], qh[kb], kl[2*s], kl[2*s+1]);
                    mma_bf16(acc[s], ql[kb], kh[2*s], kh[2*s+1]);
                }
            }
            // ---- normalize, write P, build P A-fragments ----
            uint32_t pfh[4], pfl[4];
            #pragma unroll
            for (int s = 0; s < 2; s++) {
                const int col = j0 + p * 16 + s * 8 + (lane & 3) * 2;
                const int mk0 = __ldg(mrow + col);
                const int mk1 = __ldg(mrow + col + 1);
                float v0 = mk0 ? acc[s][0] * 0.125f : -1e9f;
                float v1 = mk1 ? acc[s][1] * 0.125f : -1e9f;
                float v2 = mk0 ? acc[s][2] * 0.125f : -1e9f;
                float v3 = mk1 ? acc[s][3] * 0.125f : -1e9f;
                float p0 = __expf(v0 - mm0) * ii0;
                float p1 = __expf(v1 - mm0) * ii0;
                float p2 = __expf(v2 - mm1) * ii1;
                float p3 = __expf(v3 - mm1) * ii1;
                *(float2*)(Prow0 + col) = make_float2(p0, p1);
                *(float2*)(Prow1 + col) = make_float2(p2, p3);
                // bf16 hi/lo split of P
                __nv_bfloat16 h0 = __float2bfloat16(p0), h1 = __float2bfloat16(p1);
                __nv_bfloat16 h2 = __float2bfloat16(p2), h3 = __float2bfloat16(p3);
                pfh[s*2+0] = (uint32_t)__bfloat16_as_ushort(h0) | ((uint32_t)__bfloat16_as_ushort(h1) << 16);
                pfh[s*2+1] = (uint32_t)__bfloat16_as_ushort(h2) | ((uint32_t)__bfloat16_as_ushort(h3) << 16);
                __nv_bfloat16 l0 = __float2bfloat16(p0 - __bfloat162float(h0));
                __nv_bfloat16 l1 = __float2bfloat16(p1 - __bfloat162float(h1));
                __nv_bfloat16 l2 = __float2bfloat16(p2 - __bfloat162float(h2));
                __nv_bfloat16 l3 = __float2bfloat16(p3 - __bfloat162float(h3));
                pfl[s*2+0] = (uint32_t)__bfloat16_as_ushort(l0) | ((uint32_t)__bfloat16_as_ushort(l1) << 16);
                pfl[s*2+1] = (uint32_t)__bfloat16_as_ushort(l2) | ((uint32_t)__bfloat16_as_ushort(l3) << 16);
            }
            // ---- P@V for this 16-key block ----
            #pragma unroll
            for (int gv = 0; gv < 4; gv++) {
                uint32_t vh[4], vl[4];
                const uint32_t off = (uint32_t)((gv * 16 + bfrag_row) * (PITCH * 2) + p * 32 + bfrag_koff);
                ldsm_x4(vh, vh_base + off);
                ldsm_x4(vl, vl_base + off);
                #pragma unroll
                for (int s = 0; s < 2; s++) {
                    float* cc = ctx[gv * 2 + s];
                    mma_bf16(cc, pfh, vh[2*s], vh[2*s+1]);
                    mma_bf16(cc, pfh, vl[2*s], vl[2*s+1]);
                    mma_bf16(cc, pfl, vh[2*s], vh[2*s+1]);
                }
            }
        }
    }

    // Epilogue: ctx rows -> g_ctx[B,S,W] layout
    #pragma unroll
    for (int ni = 0; ni < 8; ni++) {
        const int col = (ni >> 1) * 16 + (ni & 1) * 8 + (lane & 3) * 2;
        float* op0 = g_ctx + ((size_t)b * Sq + i0 + r0) * Wd + h * Dd + col;
        float* op1 = g_ctx + ((size_t)b * Sq + i0 + r0 + 8) * Wd + h * Dd + col;
        *(float2*)op0 = make_float2(ctx[ni][0], ctx[ni][1]);
        *(float2*)op1 = make_float2(ctx[ni][2], ctx[ni][3]);
    }
}

// ---------------------------------------------------------------------------
extern "C" void kernel_launch(void* const* d_in, const int* in_sizes, int n_in,
                              void* d_out, int out_size) {
    const float* query = (const float*)d_in[0];
    const int*   mask  = (const int*)d_in[1];
    const float* q_w = (const float*)d_in[2];
    const float* q_b = (const float*)d_in[3];
    const float* k_w = (const float*)d_in[4];
    const float* k_b = (const float*)d_in[5];
    const float* v_w = (const float*)d_in[6];
    const float* v_b = (const float*)d_in[7];
    const float* o_w = (const float*)d_in[8];
    const float* o_b = (const float*)d_in[9];

    float* out = (float*)d_out;
    float* attn = ((long long)out_size >= OUT_ELEMS + ATTN_ELEMS) ? out + OUT_ELEMS : nullptr;

    cudaFuncSetAttribute(stats_mma, cudaFuncAttributeMaxDynamicSharedMemorySize, STATS_SMEM);
    cudaFuncSetAttribute(av_mma, cudaFuncAttributeMaxDynamicSharedMemorySize, AV_SMEM);

    proj_mma<<<dim3(6, 32, 3), 256>>>(0, query, Eq,
                                      q_w, q_b, k_w, k_b, v_w, v_b, nullptr);
    stats_mma<<<dim3(8, NZ), 256, STATS_SMEM>>>(mask);
    av_mma<<<dim3(8, NZ), 256, AV_SMEM>>>(mask, attn);
    proj_mma<<<dim3(6, 32, 1), 256>>>(1, nullptr, Wd,
                                      o_w, o_b, nullptr, nullptr, nullptr, nullptr, out);
}